// round 13
// baseline (speedup 1.0000x reference)
#include <cuda_runtime.h>
#include <math.h>
#include <stdint.h>

#define KK 64
#define PP 256
#define RR 16
#define MROWS 128                       // rows per CTA
#define NPASS 16                        // B passes of 64 j-rows (4 comps each)

// smem: X tile 32KB | B stage0 16KB | B stage1 16KB | red 512B | w 256B | meta 16B
#define SMO_X 0
#define SMO_B0 32768
#define SMO_B1 49152
#define SMO_RED 65536
#define SMO_W   (65536 + 512)
#define SMO_META (65536 + 512 + 256)
#define SMEM_TOTAL (65536 + 512 + 256 + 16)

// ---- device globals (no allocation allowed) ----
__device__ __align__(16) int8_t g_B[KK * RR * PP];    // s8(256*y), [j][p]
__device__ float  g_logdet[KK];
__device__ double g_acc;
__device__ unsigned int g_count;

// ================= helpers =================
__device__ __forceinline__ uint32_t smem_u32(const void* p) {
    uint32_t a;
    asm("{ .reg .u64 t; cvta.to.shared.u64 t, %1; cvt.u32.u64 %0, t; }"
        : "=r"(a) : "l"(p));
    return a;
}
__device__ __forceinline__ void ldsm4(uint32_t* r, uint32_t addr) {
    asm volatile("ldmatrix.sync.aligned.m8n8.x4.shared.b16 {%0,%1,%2,%3}, [%4];"
                 : "=r"(r[0]), "=r"(r[1]), "=r"(r[2]), "=r"(r[3]) : "r"(addr));
}
__device__ __forceinline__ void mma_s8(int32_t* c, const uint32_t* a,
                                       uint32_t b0, uint32_t b1) {
    asm volatile(
        "mma.sync.aligned.m16n8k32.row.col.s32.s8.s8.s32 "
        "{%0,%1,%2,%3}, {%4,%5,%6,%7}, {%8,%9}, {%0,%1,%2,%3};"
        : "+r"(c[0]), "+r"(c[1]), "+r"(c[2]), "+r"(c[3])
        : "r"(a[0]), "r"(a[1]), "r"(a[2]), "r"(a[3]), "r"(b0), "r"(b1));
}
__device__ __forceinline__ void cp16(uint32_t dst, const void* src) {
    asm volatile("cp.async.cg.shared.global [%0], [%1], 16;"
                 :: "r"(dst), "l"(src) : "memory");
}
__device__ __forceinline__ void cp_commit() {
    asm volatile("cp.async.commit_group;" ::: "memory");
}
template <int NN>
__device__ __forceinline__ void cp_wait() {
    asm volatile("cp.async.wait_group %0;" :: "n"(NN) : "memory");
}
__device__ __forceinline__ int clamp127(int v) {
    return v < -127 ? -127 : (v > 127 ? 127 : v);
}
// pack 4 floats (already scaled) -> 4 s8 bytes (byte0 = a)
__device__ __forceinline__ uint32_t pack4_s8(float a, float b, float c, float d) {
    int ia = clamp127(__float2int_rn(a));
    int ib = clamp127(__float2int_rn(b));
    int ic = clamp127(__float2int_rn(c));
    int id = clamp127(__float2int_rn(d));
    return (uint32_t)(ia & 0xFF) | ((uint32_t)(ib & 0xFF) << 8)
         | ((uint32_t)(ic & 0xFF) << 16) | ((uint32_t)id << 24);
}

// ================= prep1: per-k Cholesky of I+M^T M, logdet, B = s8(256*(M L^{-T})^T) ===
__global__ void prep1_kernel(const float* __restrict__ M) {
    __shared__ float sM[PP * RR];
    __shared__ float sD[RR][RR + 1];
    const int k = blockIdx.x;
    const int tid = threadIdx.x;      // 256

    if (k == 0 && tid == 0) { g_acc = 0.0; g_count = 0u; }

    const float4* Mg = (const float4*)(M + (size_t)k * PP * RR);
    float4* sM4 = (float4*)sM;
#pragma unroll
    for (int i = 0; i < 4; ++i) sM4[tid + i * 256] = Mg[tid + i * 256];
    __syncthreads();

    {   // D[r][s] with 4 independent partial chains
        int r = tid >> 4, s = tid & 15;
        float d0 = 0.f, d1 = 0.f, d2 = 0.f, d3 = 0.f;
        for (int p = 0; p < PP; p += 4) {
            d0 += sM[(p + 0) * RR + r] * sM[(p + 0) * RR + s];
            d1 += sM[(p + 1) * RR + r] * sM[(p + 1) * RR + s];
            d2 += sM[(p + 2) * RR + r] * sM[(p + 2) * RR + s];
            d3 += sM[(p + 3) * RR + r] * sM[(p + 3) * RR + s];
        }
        sD[r][s] = ((r == s) ? 1.0f : 0.0f) + (d0 + d1) + (d2 + d3);
    }
    __syncthreads();

    if (tid == 0) {
        float logdet = 0.f;
        for (int j = 0; j < RR; ++j) {
            float sum = sD[j][j];
            for (int t = 0; t < j; ++t) sum -= sD[j][t] * sD[j][t];
            float Ljj = sqrtf(sum);
            sD[j][j] = Ljj;
            logdet += 2.0f * logf(Ljj);
            float inv = 1.0f / Ljj;
            for (int i = j + 1; i < RR; ++i) {
                float s2 = sD[i][j];
                for (int t = 0; t < j; ++t) s2 -= sD[i][t] * sD[j][t];
                sD[i][j] = s2 * inv;
            }
        }
        g_logdet[k] = logdet;
    }
    __syncthreads();

    {   // forward solve L y = m_p; scatter s8(256*y) to g_B[(k*16+i)*256 + p]
        const int p = tid;
        float y[RR];
#pragma unroll
        for (int i = 0; i < RR; ++i) {
            float s2 = sM[p * RR + i];
#pragma unroll
            for (int j = 0; j < RR; ++j)
                if (j < i) s2 -= sD[i][j] * y[j];
            y[i] = s2 / sD[i][i];
        }
#pragma unroll
        for (int i = 0; i < RR; ++i)
            g_B[(size_t)(k * RR + i) * PP + p] =
                (int8_t)clamp127(__float2int_rn(256.0f * y[i]));
    }
}

// ================= main: s8 IMMA GEMM + fused ACG epilogue + finalize ===============
// 256 thr = 8 warps, 3 CTAs/SM. Warp w: rows 32*(w&3)..+31, comps (pass*4 + (w>>2)*2 ..+1).
// B pass = 64 j-rows (16KB), double-buffered via cp.async. Last CTA writes the output.
__global__ void __launch_bounds__(256, 3)
main_mma_kernel(const float* __restrict__ X, const float* __restrict__ pi,
                float* __restrict__ out, int N, int nblocks) {
    extern __shared__ char smem[];
    char* sX = smem + SMO_X;
    float* sRed = (float*)(smem + SMO_RED);
    float* sW = (float*)(smem + SMO_W);
    float* sMeta = (float*)(smem + SMO_META);

    const int tid = threadIdx.x;
    const int w = tid >> 5, l = tid & 31;
    const int base = blockIdx.x * MROWS;

    const uint32_t sbX = smem_u32(sX);
    const uint32_t sbB0 = smem_u32(smem + SMO_B0);

    // per-thread cp.async addressing for a 64-row B pass tile (4 uint4 each)
    uint32_t bDst[4];
    const char* bSrc[4];
#pragma unroll
    for (int i = 0; i < 4; ++i) {
        int u = tid + i * 256;                 // 0..1023 uint4s
        int jl = u >> 4, cg = u & 15;          // 16 units of 16B per 256B row
        bDst[i] = (uint32_t)jl * 256u + (uint32_t)((cg ^ (jl & 7)) << 4);
        bSrc[i] = (const char*)g_B + (size_t)u * 16;
    }

    // prefetch B pass 0 into stage 0 (streams under the X load below)
#pragma unroll
    for (int i = 0; i < 4; ++i) cp16(sbB0 + bDst[i], bSrc[i]);
    cp_commit();

    // ---- per-CTA mixture weights: w_k = exp(c_k - cmax), warp 0 only ----
    if (w == 0) {
        float p1 = pi[l], p2 = pi[l + 32];
        float ld1 = g_logdet[l], ld2 = g_logdet[l + 32];
        float m = fmaxf(p1, p2);
#pragma unroll
        for (int o = 16; o > 0; o >>= 1) m = fmaxf(m, __shfl_xor_sync(0xffffffffu, m, o));
        float s = expf(p1 - m) + expf(p2 - m);
#pragma unroll
        for (int o = 16; o > 0; o >>= 1) s += __shfl_xor_sync(0xffffffffu, s, o);
        float lse = m + logf(s);
        float c1 = (p1 - lse) - 0.5f * ld1;
        float c2 = (p2 - lse) - 0.5f * ld2;
        float cm = fmaxf(c1, c2);
#pragma unroll
        for (int o = 16; o > 0; o >>= 1) cm = fmaxf(cm, __shfl_xor_sync(0xffffffffu, cm, o));
        sW[l] = expf(c1 - cm);
        sW[l + 32] = expf(c2 - cm);
        if (l == 0) sMeta[0] = cm;
    }

    if (tid < 128) sRed[tid] = 0.f;

    // ---- load X tile (128 x 256 fp32 -> s8(256x)), crosswise swizzle ----
#pragma unroll
    for (int i = 0; i < 8; ++i) {
        int u = tid + i * 256;              // 0..2047 groups of 16 floats
        int row = u >> 4, c16 = u & 15;
        int n = base + row; if (n > N - 1) n = N - 1;
        const float4* src = (const float4*)(X + (size_t)n * PP + c16 * 16);
        float4 v0 = src[0], v1 = src[1], v2 = src[2], v3 = src[3];
        uint4 val;
        val.x = pack4_s8(256.f * v0.x, 256.f * v0.y, 256.f * v0.z, 256.f * v0.w);
        val.y = pack4_s8(256.f * v1.x, 256.f * v1.y, 256.f * v1.z, 256.f * v1.w);
        val.z = pack4_s8(256.f * v2.x, 256.f * v2.y, 256.f * v2.z, 256.f * v2.w);
        val.w = pack4_s8(256.f * v3.x, 256.f * v3.y, 256.f * v3.z, 256.f * v3.w);
        uint32_t byte = (uint32_t)row * 256u + (uint32_t)((c16 ^ (row & 7)) << 4);
        *(uint4*)(sX + byte) = val;
    }

    // ---- per-lane ldmatrix addressing (row stride 256B, 16B col units) ----
    const int R0 = (w & 3) * 32;
    const int rA = R0 + (l & 7) + ((l >> 3) & 1) * 8;
    const uint32_t koffA = (uint32_t)(l >> 4);          // 16B col-group +0/+1
    const uint32_t baseA0 = sbX + (uint32_t)rA * 256u;
    const uint32_t baseA1 = baseA0 + 16u * 256u;
    const uint32_t swA = (uint32_t)(rA & 7);

    const int cgrp = w >> 2;                            // comp-half of pass (2 comps each)
    const int nIn = (l & 7) + ((l >> 4) & 1) * 8;
    const uint32_t koffB = (uint32_t)((l >> 3) & 1);
    const uint32_t swB = (uint32_t)(nIn & 7);

    float s[2][2] = {{0.f, 0.f}, {0.f, 0.f}};

    for (int cb = 0; cb < NPASS; ++cb) {
        __syncthreads();     // X/sW ready (cb=0) / all warps done reading stage (cb+1)&1

        if (cb + 1 < NPASS) {   // prefetch next pass into the other stage
            const uint32_t sbNext = sbB0 + (uint32_t)((cb + 1) & 1) * 16384u;
            const size_t srcOff = (size_t)(cb + 1) * 16384;   // 64 j-rows * 256 B
#pragma unroll
            for (int i = 0; i < 4; ++i) cp16(sbNext + bDst[i], bSrc[i] + srcOff);
            cp_commit();
            cp_wait<1>();    // current pass's B has landed
        } else {
            cp_wait<0>();
        }
        __syncthreads();     // B(cb) visible to all threads

        const uint32_t stage = sbB0 + (uint32_t)(cb & 1) * 16384u;

        int32_t acc[2][2][2][4];
#pragma unroll
        for (int i = 0; i < 2; ++i)
#pragma unroll
            for (int c = 0; c < 2; ++c)
#pragma unroll
                for (int t = 0; t < 2; ++t)
#pragma unroll
                    for (int e = 0; e < 4; ++e) acc[i][c][t][e] = 0;

#pragma unroll
        for (int ks = 0; ks < 8; ++ks) {                 // k32 steps over K=256
            uint32_t a0[4], a1[4];
            uint32_t gA = ((2u * ks + koffA) ^ swA) << 4;
            ldsm4(a0, baseA0 + gA);
            ldsm4(a1, baseA1 + gA);
            uint32_t gB = ((2u * ks + koffB) ^ swB) << 4;
#pragma unroll
            for (int c = 0; c < 2; ++c) {                // comp = 16 j-rows
                uint32_t bb[4];
                uint32_t rowB = (uint32_t)(cgrp * 32 + c * 16 + nIn) * 256u;
                ldsm4(bb, stage + rowB + gB);
                mma_s8(acc[0][c][0], a0, bb[0], bb[1]);
                mma_s8(acc[0][c][1], a0, bb[2], bb[3]);
                mma_s8(acc[1][c][0], a1, bb[0], bb[1]);
                mma_s8(acc[1][c][1], a1, bb[2], bb[3]);
            }
        }

        // ---- epilogue for this warp's 2 comps of the pass ----
#pragma unroll
        for (int c = 0; c < 2; ++c) {
            const int kg = cb * 4 + cgrp * 2 + c;
            const float wk = sW[kg];
#pragma unroll
            for (int i = 0; i < 2; ++i) {
#pragma unroll
                for (int h = 0; h < 2; ++h) {
                    float y0 = (float)acc[i][c][0][2 * h];
                    float y1 = (float)acc[i][c][0][2 * h + 1];
                    float y2 = (float)acc[i][c][1][2 * h];
                    float y3 = (float)acc[i][c][1][2 * h + 1];
                    float q = y0 * y0 + y1 * y1 + y2 * y2 + y3 * y3;
                    q += __shfl_xor_sync(0xffffffffu, q, 1);
                    q += __shfl_xor_sync(0xffffffffu, q, 2);
                    // scale back the 256x256 input scaling: quad = q / 2^32
                    float pdf = fmaf(q, -2.3283064365386963e-10f, 1.0f);
                    float p2 = pdf * pdf;   // ^2
                    p2 = p2 * p2;           // ^4
                    p2 = p2 * p2;           // ^8
                    p2 = p2 * p2;           // ^16
                    p2 = p2 * p2;           // ^32
                    p2 = p2 * p2;           // ^64
                    p2 = p2 * p2;           // ^128
                    s[i][h] += __fdividef(wk, p2);
                }
            }
        }
    }

    // ---- combine the two comp-halves (warps w and w+4 share rows) ----
    if ((l & 3) == 0) {
        int g = l >> 2;
#pragma unroll
        for (int i = 0; i < 2; ++i)
#pragma unroll
            for (int h = 0; h < 2; ++h)
                atomicAdd(&sRed[R0 + 16 * i + 8 * h + g], s[i][h]);
    }
    __syncthreads();

    float val = 0.f;
    if (tid < 128) {
        int n = base + tid;
        val = (n < N) ? logf(sRed[tid]) : 0.f;
    }
    __syncthreads();
#pragma unroll
    for (int o = 16; o > 0; o >>= 1) val += __shfl_xor_sync(0xffffffffu, val, o);
    if (l == 0) sRed[w] = val;
    __syncthreads();
    if (tid == 0) {
        float bs = 0.f;
#pragma unroll
        for (int i = 0; i < 8; ++i) bs += sRed[i];
        atomicAdd(&g_acc, (double)bs);
        __threadfence();
        unsigned int old = atomicAdd(&g_count, 1u);
        if (old == (unsigned int)(nblocks - 1)) {
            double tot = atomicAdd(&g_acc, 0.0);
            const double logSA =
                lgamma(128.0) - log(2.0) - 128.0 * log(3.14159265358979323846);
            out[0] = (float)(tot + (double)N * (logSA + (double)sMeta[0]));
        }
    }
}

extern "C" void kernel_launch(void* const* d_in, const int* in_sizes, int n_in,
                              void* d_out, int out_size) {
    const float* X = nullptr;
    const float* M = nullptr;
    const float* pi = nullptr;
    int N = 0;
    for (int i = 0; i < n_in; ++i) {
        int sz = in_sizes[i];
        if (sz == KK) pi = (const float*)d_in[i];
        else if (sz == KK * PP * RR) M = (const float*)d_in[i];
        else { X = (const float*)d_in[i]; N = sz / PP; }
    }

    static bool attr_done = false;
    if (!attr_done) {
        cudaFuncSetAttribute(main_mma_kernel,
                             cudaFuncAttributeMaxDynamicSharedMemorySize, SMEM_TOTAL);
        attr_done = true;
    }

    prep1_kernel<<<KK, 256>>>(M);
    int nb = (N + MROWS - 1) / MROWS;
    main_mma_kernel<<<nb, 256, SMEM_TOTAL>>>(X, pi, (float*)d_out, N, nb);
}

// round 14
// speedup vs baseline: 1.1314x; 1.1314x over previous
#include <cuda_runtime.h>
#include <math.h>
#include <stdint.h>

#define KK 64
#define PP 256
#define RR 16
#define MROWS 128                       // rows per CTA

// smem: X tile 32KB | B stage0 32KB | B stage1 32KB | red 512B | w 256B | meta 16B
#define SMO_X 0
#define SMO_B0 32768
#define SMO_B1 65536
#define SMO_RED 98304
#define SMO_W   (98304 + 512)
#define SMO_META (98304 + 512 + 256)
#define SMEM_TOTAL (98304 + 512 + 256 + 16)

// ---- device globals (no allocation allowed) ----
__device__ __align__(16) int8_t g_B[KK * RR * PP];    // s8(256*y), [j][p]
__device__ float  g_logdet[KK];
__device__ double g_acc;
__device__ unsigned int g_count;

// ================= helpers =================
__device__ __forceinline__ uint32_t smem_u32(const void* p) {
    uint32_t a;
    asm("{ .reg .u64 t; cvta.to.shared.u64 t, %1; cvt.u32.u64 %0, t; }"
        : "=r"(a) : "l"(p));
    return a;
}
__device__ __forceinline__ void ldsm4(uint32_t* r, uint32_t addr) {
    asm volatile("ldmatrix.sync.aligned.m8n8.x4.shared.b16 {%0,%1,%2,%3}, [%4];"
                 : "=r"(r[0]), "=r"(r[1]), "=r"(r[2]), "=r"(r[3]) : "r"(addr));
}
__device__ __forceinline__ void mma_s8(int32_t* c, const uint32_t* a,
                                       uint32_t b0, uint32_t b1) {
    asm volatile(
        "mma.sync.aligned.m16n8k32.row.col.s32.s8.s8.s32 "
        "{%0,%1,%2,%3}, {%4,%5,%6,%7}, {%8,%9}, {%0,%1,%2,%3};"
        : "+r"(c[0]), "+r"(c[1]), "+r"(c[2]), "+r"(c[3])
        : "r"(a[0]), "r"(a[1]), "r"(a[2]), "r"(a[3]), "r"(b0), "r"(b1));
}
__device__ __forceinline__ void cp16(uint32_t dst, const void* src) {
    asm volatile("cp.async.cg.shared.global [%0], [%1], 16;"
                 :: "r"(dst), "l"(src) : "memory");
}
__device__ __forceinline__ void cp_commit() {
    asm volatile("cp.async.commit_group;" ::: "memory");
}
template <int NN>
__device__ __forceinline__ void cp_wait() {
    asm volatile("cp.async.wait_group %0;" :: "n"(NN) : "memory");
}
__device__ __forceinline__ int clamp127(int v) {
    return v < -127 ? -127 : (v > 127 ? 127 : v);
}
// pack 4 floats (already scaled) -> 4 s8 bytes (byte0 = a)
__device__ __forceinline__ uint32_t pack4_s8(float a, float b, float c, float d) {
    int ia = clamp127(__float2int_rn(a));
    int ib = clamp127(__float2int_rn(b));
    int ic = clamp127(__float2int_rn(c));
    int id = clamp127(__float2int_rn(d));
    return (uint32_t)(ia & 0xFF) | ((uint32_t)(ib & 0xFF) << 8)
         | ((uint32_t)(ic & 0xFF) << 16) | ((uint32_t)id << 24);
}

#define SMSTR 17   // padded row stride (floats) for sM: conflict-free lane-p access

// ================= prep1: per-k Cholesky of I+M^T M, logdet, B = s8(256*(M L^{-T})^T) ===
__global__ void prep1_kernel(const float* __restrict__ M) {
    __shared__ float sM[PP * SMSTR];     // [p][r], stride 17
    __shared__ float sD[RR][RR + 1];
    __shared__ float sInv[RR];
    const int k = blockIdx.x;
    const int tid = threadIdx.x;      // 256
    const int l = tid & 31;

    if (k == 0 && tid == 0) { g_acc = 0.0; g_count = 0u; }

    // load M_k: each thread 4 float4 = one row p per 4 threads... simple: 16 floats/thread
    {
        const float4* Mg = (const float4*)(M + (size_t)k * PP * RR);
#pragma unroll
        for (int i = 0; i < 4; ++i) {
            int u = tid + i * 256;        // float4 index: p = u>>2, r0 = (u&3)*4
            float4 v = Mg[u];
            int p = u >> 2, r0 = (u & 3) * 4;
            float* dst = &sM[p * SMSTR + r0];
            dst[0] = v.x; dst[1] = v.y; dst[2] = v.z; dst[3] = v.w;
        }
    }
    __syncthreads();

    {   // D[r][s] with 4 independent partial chains
        int r = tid >> 4, s = tid & 15;
        float d0 = 0.f, d1 = 0.f, d2 = 0.f, d3 = 0.f;
        for (int p = 0; p < PP; p += 4) {
            d0 += sM[(p + 0) * SMSTR + r] * sM[(p + 0) * SMSTR + s];
            d1 += sM[(p + 1) * SMSTR + r] * sM[(p + 1) * SMSTR + s];
            d2 += sM[(p + 2) * SMSTR + r] * sM[(p + 2) * SMSTR + s];
            d3 += sM[(p + 3) * SMSTR + r] * sM[(p + 3) * SMSTR + s];
        }
        sD[r][s] = ((r == s) ? 1.0f : 0.0f) + (d0 + d1) + (d2 + d3);
    }
    __syncthreads();

    // warp-parallel right-looking Cholesky (warp 0); logdet = 2*log(prod Ljj)
    if (tid < 32) {
        float prodL = 1.0f;
#pragma unroll
        for (int j = 0; j < RR; ++j) {
            if (l == 0) {
                float Ljj = sqrtf(sD[j][j]);
                sD[j][j] = Ljj;
                sInv[j] = 1.0f / Ljj;
            }
            __syncwarp();
            float rinv = sInv[j];
            if (l == 0) prodL *= sD[j][j];
            if (l > j && l < RR) sD[l][j] *= rinv;
            __syncwarp();
            if (l > j && l < RR) {
                float Llj = sD[l][j];
                for (int t = j + 1; t <= l; ++t) sD[l][t] -= Llj * sD[t][j];
            }
            __syncwarp();
        }
        if (l == 0) g_logdet[k] = 2.0f * logf(prodL);
    }
    __syncthreads();

    {   // forward solve L y = m_p (multiply by precomputed 1/L_ii); quantize s8(256*y)
        const int p = tid;
        float y[RR];
        float m[RR];
#pragma unroll
        for (int i = 0; i < RR; ++i) m[i] = sM[p * SMSTR + i];   // conflict-free (stride 17)
#pragma unroll
        for (int i = 0; i < RR; ++i) {
            float s2 = m[i];
#pragma unroll
            for (int j = 0; j < RR; ++j)
                if (j < i) s2 -= sD[i][j] * y[j];
            y[i] = s2 * sInv[i];
        }
#pragma unroll
        for (int i = 0; i < RR; ++i)
            g_B[(size_t)(k * RR + i) * PP + p] =
                (int8_t)clamp127(__float2int_rn(256.0f * y[i]));
    }
}

// ================= main: s8 IMMA GEMM + fused ACG epilogue + finalize ===============
// 256 thr = 8 warps, 2 CTAs/SM. Warp w: rows 32*(w&3)..+31, comps (pass*8 + (w>>2)*4 ..+3).
// B pass = 128 j-rows (32KB), double-buffered via cp.async. Last CTA writes the output.
__global__ void __launch_bounds__(256, 2)
main_mma_kernel(const float* __restrict__ X, const float* __restrict__ pi,
                float* __restrict__ out, int N, int nblocks) {
    extern __shared__ char smem[];
    char* sX = smem + SMO_X;
    float* sRed = (float*)(smem + SMO_RED);
    float* sW = (float*)(smem + SMO_W);
    float* sMeta = (float*)(smem + SMO_META);

    const int tid = threadIdx.x;
    const int w = tid >> 5, l = tid & 31;
    const int base = blockIdx.x * MROWS;

    const uint32_t sbX = smem_u32(sX);
    const uint32_t sbB0 = smem_u32(smem + SMO_B0);

    // per-thread cp.async addressing for a 128-row B pass tile (8 uint4 each)
    uint32_t bDst[8];
    const char* bSrc[8];
#pragma unroll
    for (int i = 0; i < 8; ++i) {
        int u = tid + i * 256;                 // 0..2047 uint4s
        int jl = u >> 4, cg = u & 15;          // 16 units of 16B per 256B row
        bDst[i] = (uint32_t)jl * 256u + (uint32_t)((cg ^ (jl & 7)) << 4);
        bSrc[i] = (const char*)g_B + (size_t)u * 16;
    }

    // prefetch B pass 0 into stage 0 (streams under the X load below)
#pragma unroll
    for (int i = 0; i < 8; ++i) cp16(sbB0 + bDst[i], bSrc[i]);
    cp_commit();

    // ---- per-CTA mixture weights: w_k = exp(c_k - cmax), warp 0 only ----
    if (w == 0) {
        float p1 = pi[l], p2 = pi[l + 32];
        float ld1 = g_logdet[l], ld2 = g_logdet[l + 32];
        float m = fmaxf(p1, p2);
#pragma unroll
        for (int o = 16; o > 0; o >>= 1) m = fmaxf(m, __shfl_xor_sync(0xffffffffu, m, o));
        float s = expf(p1 - m) + expf(p2 - m);
#pragma unroll
        for (int o = 16; o > 0; o >>= 1) s += __shfl_xor_sync(0xffffffffu, s, o);
        float lse = m + logf(s);
        float c1 = (p1 - lse) - 0.5f * ld1;
        float c2 = (p2 - lse) - 0.5f * ld2;
        float cm = fmaxf(c1, c2);
#pragma unroll
        for (int o = 16; o > 0; o >>= 1) cm = fmaxf(cm, __shfl_xor_sync(0xffffffffu, cm, o));
        sW[l] = expf(c1 - cm);
        sW[l + 32] = expf(c2 - cm);
        if (l == 0) sMeta[0] = cm;
    }

    if (tid < 128) sRed[tid] = 0.f;

    // ---- load X tile (128 x 256 fp32 -> s8(256x)), crosswise swizzle ----
#pragma unroll
    for (int i = 0; i < 8; ++i) {
        int u = tid + i * 256;              // 0..2047 groups of 16 floats
        int row = u >> 4, c16 = u & 15;
        int n = base + row; if (n > N - 1) n = N - 1;
        const float4* src = (const float4*)(X + (size_t)n * PP + c16 * 16);
        float4 v0 = src[0], v1 = src[1], v2 = src[2], v3 = src[3];
        uint4 val;
        val.x = pack4_s8(256.f * v0.x, 256.f * v0.y, 256.f * v0.z, 256.f * v0.w);
        val.y = pack4_s8(256.f * v1.x, 256.f * v1.y, 256.f * v1.z, 256.f * v1.w);
        val.z = pack4_s8(256.f * v2.x, 256.f * v2.y, 256.f * v2.z, 256.f * v2.w);
        val.w = pack4_s8(256.f * v3.x, 256.f * v3.y, 256.f * v3.z, 256.f * v3.w);
        uint32_t byte = (uint32_t)row * 256u + (uint32_t)((c16 ^ (row & 7)) << 4);
        *(uint4*)(sX + byte) = val;
    }

    // ---- per-lane ldmatrix addressing (row stride 256B, 16B col units) ----
    const int R0 = (w & 3) * 32;
    const int rA = R0 + (l & 7) + ((l >> 3) & 1) * 8;
    const uint32_t koffA = (uint32_t)(l >> 4);          // 16B col-group +0/+1
    const uint32_t baseA0 = sbX + (uint32_t)rA * 256u;
    const uint32_t baseA1 = baseA0 + 16u * 256u;
    const uint32_t swA = (uint32_t)(rA & 7);

    const int cgrp = w >> 2;                            // comp-half of pass (4 comps each)
    const int nIn = (l & 7) + ((l >> 4) & 1) * 8;
    const uint32_t koffB = (uint32_t)((l >> 3) & 1);
    const uint32_t swB = (uint32_t)(nIn & 7);

    float s[2][2] = {{0.f, 0.f}, {0.f, 0.f}};

    for (int cb = 0; cb < 8; ++cb) {
        __syncthreads();     // X/sW ready (cb=0) / all warps done reading stage (cb+1)&1

        if (cb + 1 < 8) {    // prefetch next pass into the other stage
            const uint32_t sbNext = sbB0 + (uint32_t)((cb + 1) & 1) * 32768u;
            const size_t srcOff = (size_t)(cb + 1) * 32768;   // 128 j-rows * 256 B
#pragma unroll
            for (int i = 0; i < 8; ++i) cp16(sbNext + bDst[i], bSrc[i] + srcOff);
            cp_commit();
            cp_wait<1>();    // current pass's B has landed
        } else {
            cp_wait<0>();
        }
        __syncthreads();     // B(cb) visible to all threads

        const uint32_t stage = sbB0 + (uint32_t)(cb & 1) * 32768u;

        int32_t acc[2][4][2][4];
#pragma unroll
        for (int i = 0; i < 2; ++i)
#pragma unroll
            for (int c = 0; c < 4; ++c)
#pragma unroll
                for (int t = 0; t < 2; ++t)
#pragma unroll
                    for (int e = 0; e < 4; ++e) acc[i][c][t][e] = 0;

#pragma unroll
        for (int ks = 0; ks < 8; ++ks) {                 // k32 steps over K=256
            uint32_t a0[4], a1[4];
            uint32_t gA = ((2u * ks + koffA) ^ swA) << 4;
            ldsm4(a0, baseA0 + gA);
            ldsm4(a1, baseA1 + gA);
            uint32_t gB = ((2u * ks + koffB) ^ swB) << 4;
#pragma unroll
            for (int c = 0; c < 4; ++c) {                // comp = 16 j-rows
                uint32_t bb[4];
                uint32_t rowB = (uint32_t)(cgrp * 64 + c * 16 + nIn) * 256u;
                ldsm4(bb, stage + rowB + gB);
                mma_s8(acc[0][c][0], a0, bb[0], bb[1]);
                mma_s8(acc[0][c][1], a0, bb[2], bb[3]);
                mma_s8(acc[1][c][0], a1, bb[0], bb[1]);
                mma_s8(acc[1][c][1], a1, bb[2], bb[3]);
            }
        }

        // ---- epilogue for this warp's 4 comps of the pass ----
#pragma unroll
        for (int c = 0; c < 4; ++c) {
            const int kg = cb * 8 + cgrp * 4 + c;
            const float wk = sW[kg];
#pragma unroll
            for (int i = 0; i < 2; ++i) {
#pragma unroll
                for (int h = 0; h < 2; ++h) {
                    float y0 = (float)acc[i][c][0][2 * h];
                    float y1 = (float)acc[i][c][0][2 * h + 1];
                    float y2 = (float)acc[i][c][1][2 * h];
                    float y3 = (float)acc[i][c][1][2 * h + 1];
                    float q = y0 * y0 + y1 * y1 + y2 * y2 + y3 * y3;
                    q += __shfl_xor_sync(0xffffffffu, q, 1);
                    q += __shfl_xor_sync(0xffffffffu, q, 2);
                    // scale back the 256x256 input scaling: quad = q / 2^32
                    float pdf = fmaf(q, -2.3283064365386963e-10f, 1.0f);
                    float p2 = pdf * pdf;   // ^2
                    p2 = p2 * p2;           // ^4
                    p2 = p2 * p2;           // ^8
                    p2 = p2 * p2;           // ^16
                    p2 = p2 * p2;           // ^32
                    p2 = p2 * p2;           // ^64
                    p2 = p2 * p2;           // ^128
                    s[i][h] += __fdividef(wk, p2);
                }
            }
        }
    }

    // ---- combine the two comp-halves (warps w and w+4 share rows) ----
    if ((l & 3) == 0) {
        int g = l >> 2;
#pragma unroll
        for (int i = 0; i < 2; ++i)
#pragma unroll
            for (int h = 0; h < 2; ++h)
                atomicAdd(&sRed[R0 + 16 * i + 8 * h + g], s[i][h]);
    }
    __syncthreads();

    float val = 0.f;
    if (tid < 128) {
        int n = base + tid;
        val = (n < N) ? logf(sRed[tid]) : 0.f;
    }
    __syncthreads();
#pragma unroll
    for (int o = 16; o > 0; o >>= 1) val += __shfl_xor_sync(0xffffffffu, val, o);
    if (l == 0) sRed[w] = val;
    __syncthreads();
    if (tid == 0) {
        float bs = 0.f;
#pragma unroll
        for (int i = 0; i < 8; ++i) bs += sRed[i];
        atomicAdd(&g_acc, (double)bs);
        __threadfence();
        unsigned int old = atomicAdd(&g_count, 1u);
        if (old == (unsigned int)(nblocks - 1)) {
            double tot = atomicAdd(&g_acc, 0.0);
            const double logSA =
                lgamma(128.0) - log(2.0) - 128.0 * log(3.14159265358979323846);
            out[0] = (float)(tot + (double)N * (logSA + (double)sMeta[0]));
        }
    }
}

extern "C" void kernel_launch(void* const* d_in, const int* in_sizes, int n_in,
                              void* d_out, int out_size) {
    const float* X = nullptr;
    const float* M = nullptr;
    const float* pi = nullptr;
    int N = 0;
    for (int i = 0; i < n_in; ++i) {
        int sz = in_sizes[i];
        if (sz == KK) pi = (const float*)d_in[i];
        else if (sz == KK * PP * RR) M = (const float*)d_in[i];
        else { X = (const float*)d_in[i]; N = sz / PP; }
    }

    static bool attr_done = false;
    if (!attr_done) {
        cudaFuncSetAttribute(main_mma_kernel,
                             cudaFuncAttributeMaxDynamicSharedMemorySize, SMEM_TOTAL);
        attr_done = true;
    }

    prep1_kernel<<<KK, 256>>>(M);
    int nb = (N + MROWS - 1) / MROWS;
    main_mma_kernel<<<nb, 256, SMEM_TOTAL>>>(X, pi, (float*)d_out, N, nb);
}

// round 15
// speedup vs baseline: 1.1344x; 1.0026x over previous
#include <cuda_runtime.h>
#include <math.h>
#include <stdint.h>

#define KK 64
#define PP 256
#define RR 16
#define MROWS 128                       // rows per CTA

// smem: X tile 32KB | B stage0 32KB | B stage1 32KB | red 512B | w 256B | meta 16B
#define SMO_X 0
#define SMO_B0 32768
#define SMO_B1 65536
#define SMO_RED 98304
#define SMO_W   (98304 + 512)
#define SMO_META (98304 + 512 + 256)
#define SMEM_TOTAL (98304 + 512 + 256 + 16)

// ---- device globals (no allocation allowed) ----
__device__ __align__(16) int8_t g_B[KK * RR * PP];    // s8(256*y), [j][p]
__device__ float  g_logdet[KK];
__device__ double g_acc;
__device__ unsigned int g_count;

// ================= helpers =================
__device__ __forceinline__ uint32_t smem_u32(const void* p) {
    uint32_t a;
    asm("{ .reg .u64 t; cvta.to.shared.u64 t, %1; cvt.u32.u64 %0, t; }"
        : "=r"(a) : "l"(p));
    return a;
}
__device__ __forceinline__ void ldsm4(uint32_t* r, uint32_t addr) {
    asm volatile("ldmatrix.sync.aligned.m8n8.x4.shared.b16 {%0,%1,%2,%3}, [%4];"
                 : "=r"(r[0]), "=r"(r[1]), "=r"(r[2]), "=r"(r[3]) : "r"(addr));
}
__device__ __forceinline__ void mma_s8(int32_t* c, const uint32_t* a,
                                       uint32_t b0, uint32_t b1) {
    asm volatile(
        "mma.sync.aligned.m16n8k32.row.col.s32.s8.s8.s32 "
        "{%0,%1,%2,%3}, {%4,%5,%6,%7}, {%8,%9}, {%0,%1,%2,%3};"
        : "+r"(c[0]), "+r"(c[1]), "+r"(c[2]), "+r"(c[3])
        : "r"(a[0]), "r"(a[1]), "r"(a[2]), "r"(a[3]), "r"(b0), "r"(b1));
}
__device__ __forceinline__ void cp16(uint32_t dst, const void* src) {
    asm volatile("cp.async.cg.shared.global [%0], [%1], 16;"
                 :: "r"(dst), "l"(src) : "memory");
}
__device__ __forceinline__ void cp_commit() {
    asm volatile("cp.async.commit_group;" ::: "memory");
}
template <int NN>
__device__ __forceinline__ void cp_wait() {
    asm volatile("cp.async.wait_group %0;" :: "n"(NN) : "memory");
}
__device__ __forceinline__ int clamp127(int v) {
    return v < -127 ? -127 : (v > 127 ? 127 : v);
}
// pack 4 floats (already scaled) -> 4 s8 bytes (byte0 = a)
__device__ __forceinline__ uint32_t pack4_s8(float a, float b, float c, float d) {
    int ia = clamp127(__float2int_rn(a));
    int ib = clamp127(__float2int_rn(b));
    int ic = clamp127(__float2int_rn(c));
    int id = clamp127(__float2int_rn(d));
    return (uint32_t)(ia & 0xFF) | ((uint32_t)(ib & 0xFF) << 8)
         | ((uint32_t)(ic & 0xFF) << 16) | ((uint32_t)id << 24);
}

#define SMSTR 17   // padded row stride (floats) for sM: conflict-free lane-p access

// ================= prep1: per-k Cholesky of I+M^T M, logdet, B = s8(256*(M L^{-T})^T) ===
__global__ void prep1_kernel(const float* __restrict__ M) {
    __shared__ float sM[PP * SMSTR];     // [p][r], stride 17
    __shared__ float sD[RR][RR + 1];
    __shared__ float sInv[RR];
    const int k = blockIdx.x;
    const int tid = threadIdx.x;      // 256
    const int l = tid & 31;

    if (k == 0 && tid == 0) { g_acc = 0.0; g_count = 0u; }

    // load M_k: each thread 4 float4 = one row p per 4 threads... simple: 16 floats/thread
    {
        const float4* Mg = (const float4*)(M + (size_t)k * PP * RR);
#pragma unroll
        for (int i = 0; i < 4; ++i) {
            int u = tid + i * 256;        // float4 index: p = u>>2, r0 = (u&3)*4
            float4 v = Mg[u];
            int p = u >> 2, r0 = (u & 3) * 4;
            float* dst = &sM[p * SMSTR + r0];
            dst[0] = v.x; dst[1] = v.y; dst[2] = v.z; dst[3] = v.w;
        }
    }
    __syncthreads();

    {   // D[r][s] with 4 independent partial chains
        int r = tid >> 4, s = tid & 15;
        float d0 = 0.f, d1 = 0.f, d2 = 0.f, d3 = 0.f;
        for (int p = 0; p < PP; p += 4) {
            d0 += sM[(p + 0) * SMSTR + r] * sM[(p + 0) * SMSTR + s];
            d1 += sM[(p + 1) * SMSTR + r] * sM[(p + 1) * SMSTR + s];
            d2 += sM[(p + 2) * SMSTR + r] * sM[(p + 2) * SMSTR + s];
            d3 += sM[(p + 3) * SMSTR + r] * sM[(p + 3) * SMSTR + s];
        }
        sD[r][s] = ((r == s) ? 1.0f : 0.0f) + (d0 + d1) + (d2 + d3);
    }
    __syncthreads();

    // warp-parallel right-looking Cholesky (warp 0); logdet = 2*log(prod Ljj)
    if (tid < 32) {
        float prodL = 1.0f;
#pragma unroll
        for (int j = 0; j < RR; ++j) {
            if (l == 0) {
                float Ljj = sqrtf(sD[j][j]);
                sD[j][j] = Ljj;
                sInv[j] = 1.0f / Ljj;
            }
            __syncwarp();
            float rinv = sInv[j];
            if (l == 0) prodL *= sD[j][j];
            if (l > j && l < RR) sD[l][j] *= rinv;
            __syncwarp();
            if (l > j && l < RR) {
                float Llj = sD[l][j];
                for (int t = j + 1; t <= l; ++t) sD[l][t] -= Llj * sD[t][j];
            }
            __syncwarp();
        }
        if (l == 0) g_logdet[k] = 2.0f * logf(prodL);
    }
    __syncthreads();

    {   // forward solve L y = m_p (multiply by precomputed 1/L_ii); quantize s8(256*y)
        const int p = tid;
        float y[RR];
        float m[RR];
#pragma unroll
        for (int i = 0; i < RR; ++i) m[i] = sM[p * SMSTR + i];   // conflict-free (stride 17)
#pragma unroll
        for (int i = 0; i < RR; ++i) {
            float s2 = m[i];
#pragma unroll
            for (int j = 0; j < RR; ++j)
                if (j < i) s2 -= sD[i][j] * y[j];
            y[i] = s2 * sInv[i];
        }
#pragma unroll
        for (int i = 0; i < RR; ++i)
            g_B[(size_t)(k * RR + i) * PP + p] =
                (int8_t)clamp127(__float2int_rn(256.0f * y[i]));
    }
}

// ================= main: s8 IMMA GEMM + fused ACG epilogue + finalize ===============
// 256 thr = 8 warps, 2 CTAs/SM. Warp w: rows 32*(w&3)..+31, comps (pass*8 + (w>>2)*4 ..+3).
// B pass = 128 j-rows (32KB), double-buffered via cp.async. Last CTA writes the output.
__global__ void __launch_bounds__(256, 2)
main_mma_kernel(const float* __restrict__ X, const float* __restrict__ pi,
                float* __restrict__ out, int N, int nblocks) {
    extern __shared__ char smem[];
    char* sX = smem + SMO_X;
    float* sRed = (float*)(smem + SMO_RED);
    float* sW = (float*)(smem + SMO_W);
    float* sMeta = (float*)(smem + SMO_META);

    const int tid = threadIdx.x;
    const int w = tid >> 5, l = tid & 31;
    const int base = blockIdx.x * MROWS;

    const uint32_t sbX = smem_u32(sX);
    const uint32_t sbB0 = smem_u32(smem + SMO_B0);

    // per-thread cp.async addressing for a 128-row B pass tile (8 uint4 each)
    uint32_t bDst[8];
    const char* bSrc[8];
#pragma unroll
    for (int i = 0; i < 8; ++i) {
        int u = tid + i * 256;                 // 0..2047 uint4s
        int jl = u >> 4, cg = u & 15;          // 16 units of 16B per 256B row
        bDst[i] = (uint32_t)jl * 256u + (uint32_t)((cg ^ (jl & 7)) << 4);
        bSrc[i] = (const char*)g_B + (size_t)u * 16;
    }

    // prefetch B pass 0 into stage 0 (streams under the X load below)
#pragma unroll
    for (int i = 0; i < 8; ++i) cp16(sbB0 + bDst[i], bSrc[i]);
    cp_commit();

    // ---- per-CTA mixture weights: w_k = exp(c_k - cmax), warp 0 only ----
    if (w == 0) {
        float p1 = pi[l], p2 = pi[l + 32];
        float ld1 = g_logdet[l], ld2 = g_logdet[l + 32];
        float m = fmaxf(p1, p2);
#pragma unroll
        for (int o = 16; o > 0; o >>= 1) m = fmaxf(m, __shfl_xor_sync(0xffffffffu, m, o));
        float s = expf(p1 - m) + expf(p2 - m);
#pragma unroll
        for (int o = 16; o > 0; o >>= 1) s += __shfl_xor_sync(0xffffffffu, s, o);
        float lse = m + logf(s);
        float c1 = (p1 - lse) - 0.5f * ld1;
        float c2 = (p2 - lse) - 0.5f * ld2;
        float cm = fmaxf(c1, c2);
#pragma unroll
        for (int o = 16; o > 0; o >>= 1) cm = fmaxf(cm, __shfl_xor_sync(0xffffffffu, cm, o));
        sW[l] = expf(c1 - cm);
        sW[l + 32] = expf(c2 - cm);
        if (l == 0) sMeta[0] = cm;
    }

    if (tid < 128) sRed[tid] = 0.f;

    // ---- load X tile (128 x 256 fp32 -> s8(256x)), crosswise swizzle ----
#pragma unroll
    for (int i = 0; i < 8; ++i) {
        int u = tid + i * 256;              // 0..2047 groups of 16 floats
        int row = u >> 4, c16 = u & 15;
        int n = base + row; if (n > N - 1) n = N - 1;
        const float4* src = (const float4*)(X + (size_t)n * PP + c16 * 16);
        float4 v0 = src[0], v1 = src[1], v2 = src[2], v3 = src[3];
        uint4 val;
        val.x = pack4_s8(256.f * v0.x, 256.f * v0.y, 256.f * v0.z, 256.f * v0.w);
        val.y = pack4_s8(256.f * v1.x, 256.f * v1.y, 256.f * v1.z, 256.f * v1.w);
        val.z = pack4_s8(256.f * v2.x, 256.f * v2.y, 256.f * v2.z, 256.f * v2.w);
        val.w = pack4_s8(256.f * v3.x, 256.f * v3.y, 256.f * v3.z, 256.f * v3.w);
        uint32_t byte = (uint32_t)row * 256u + (uint32_t)((c16 ^ (row & 7)) << 4);
        *(uint4*)(sX + byte) = val;
    }

    // ---- per-lane ldmatrix addressing (row stride 256B, 16B col units) ----
    const int R0 = (w & 3) * 32;
    const int rA = R0 + (l & 7) + ((l >> 3) & 1) * 8;
    const uint32_t koffA = (uint32_t)(l >> 4);          // 16B col-group +0/+1
    const uint32_t baseA0 = sbX + (uint32_t)rA * 256u;
    const uint32_t baseA1 = baseA0 + 16u * 256u;
    const uint32_t swA = (uint32_t)(rA & 7);

    const int cgrp = w >> 2;                            // comp-half of pass (4 comps each)
    const int nIn = (l & 7) + ((l >> 4) & 1) * 8;
    const uint32_t koffB = (uint32_t)((l >> 3) & 1);
    const uint32_t swB = (uint32_t)(nIn & 7);

    float s[2][2] = {{0.f, 0.f}, {0.f, 0.f}};

    for (int cb = 0; cb < 8; ++cb) {
        __syncthreads();     // X/sW ready (cb=0) / all warps done reading stage (cb+1)&1

        if (cb + 1 < 8) {    // prefetch next pass into the other stage
            const uint32_t sbNext = sbB0 + (uint32_t)((cb + 1) & 1) * 32768u;
            const size_t srcOff = (size_t)(cb + 1) * 32768;   // 128 j-rows * 256 B
#pragma unroll
            for (int i = 0; i < 8; ++i) cp16(sbNext + bDst[i], bSrc[i] + srcOff);
            cp_commit();
            cp_wait<1>();    // current pass's B has landed
        } else {
            cp_wait<0>();
        }
        __syncthreads();     // B(cb) visible to all threads

        const uint32_t stage = sbB0 + (uint32_t)(cb & 1) * 32768u;

        int32_t acc[2][4][2][4];
#pragma unroll
        for (int i = 0; i < 2; ++i)
#pragma unroll
            for (int c = 0; c < 4; ++c)
#pragma unroll
                for (int t = 0; t < 2; ++t)
#pragma unroll
                    for (int e = 0; e < 4; ++e) acc[i][c][t][e] = 0;

#pragma unroll
        for (int ks = 0; ks < 8; ++ks) {                 // k32 steps over K=256
            uint32_t a0[4], a1[4];
            uint32_t gA = ((2u * ks + koffA) ^ swA) << 4;
            ldsm4(a0, baseA0 + gA);
            ldsm4(a1, baseA1 + gA);
            uint32_t gB = ((2u * ks + koffB) ^ swB) << 4;
#pragma unroll
            for (int c = 0; c < 4; ++c) {                // comp = 16 j-rows
                uint32_t bb[4];
                uint32_t rowB = (uint32_t)(cgrp * 64 + c * 16 + nIn) * 256u;
                ldsm4(bb, stage + rowB + gB);
                mma_s8(acc[0][c][0], a0, bb[0], bb[1]);
                mma_s8(acc[0][c][1], a0, bb[2], bb[3]);
                mma_s8(acc[1][c][0], a1, bb[0], bb[1]);
                mma_s8(acc[1][c][1], a1, bb[2], bb[3]);
            }
        }

        // ---- epilogue for this warp's 4 comps of the pass ----
#pragma unroll
        for (int c = 0; c < 4; ++c) {
            const int kg = cb * 8 + cgrp * 4 + c;
            const float wk = sW[kg];
#pragma unroll
            for (int i = 0; i < 2; ++i) {
#pragma unroll
                for (int h = 0; h < 2; ++h) {
                    float y0 = (float)acc[i][c][0][2 * h];
                    float y1 = (float)acc[i][c][0][2 * h + 1];
                    float y2 = (float)acc[i][c][1][2 * h];
                    float y3 = (float)acc[i][c][1][2 * h + 1];
                    float q = y0 * y0 + y1 * y1 + y2 * y2 + y3 * y3;
                    q += __shfl_xor_sync(0xffffffffu, q, 1);
                    q += __shfl_xor_sync(0xffffffffu, q, 2);
                    // scale back the 256x256 input scaling: quad = q / 2^32
                    float pdf = fmaf(q, -2.3283064365386963e-10f, 1.0f);
                    float p2 = pdf * pdf;   // ^2
                    p2 = p2 * p2;           // ^4
                    p2 = p2 * p2;           // ^8
                    p2 = p2 * p2;           // ^16
                    p2 = p2 * p2;           // ^32
                    p2 = p2 * p2;           // ^64
                    p2 = p2 * p2;           // ^128
                    s[i][h] += __fdividef(wk, p2);
                }
            }
        }
    }

    // ---- combine the two comp-halves (warps w and w+4 share rows) ----
    if ((l & 3) == 0) {
        int g = l >> 2;
#pragma unroll
        for (int i = 0; i < 2; ++i)
#pragma unroll
            for (int h = 0; h < 2; ++h)
                atomicAdd(&sRed[R0 + 16 * i + 8 * h + g], s[i][h]);
    }
    __syncthreads();

    float val = 0.f;
    if (tid < 128) {
        int n = base + tid;
        val = (n < N) ? logf(sRed[tid]) : 0.f;
    }
    __syncthreads();
#pragma unroll
    for (int o = 16; o > 0; o >>= 1) val += __shfl_xor_sync(0xffffffffu, val, o);
    if (l == 0) sRed[w] = val;
    __syncthreads();
    if (tid == 0) {
        float bs = 0.f;
#pragma unroll
        for (int i = 0; i < 8; ++i) bs += sRed[i];
        atomicAdd(&g_acc, (double)bs);
        __threadfence();
        unsigned int old = atomicAdd(&g_count, 1u);
        if (old == (unsigned int)(nblocks - 1)) {
            double tot = atomicAdd(&g_acc, 0.0);
            const double logSA =
                lgamma(128.0) - log(2.0) - 128.0 * log(3.14159265358979323846);
            out[0] = (float)(tot + (double)N * (logSA + (double)sMeta[0]));
        }
    }
}

extern "C" void kernel_launch(void* const* d_in, const int* in_sizes, int n_in,
                              void* d_out, int out_size) {
    const float* X = nullptr;
    const float* M = nullptr;
    const float* pi = nullptr;
    int N = 0;
    for (int i = 0; i < n_in; ++i) {
        int sz = in_sizes[i];
        if (sz == KK) pi = (const float*)d_in[i];
        else if (sz == KK * PP * RR) M = (const float*)d_in[i];
        else { X = (const float*)d_in[i]; N = sz / PP; }
    }

    static bool attr_done = false;
    if (!attr_done) {
        cudaFuncSetAttribute(main_mma_kernel,
                             cudaFuncAttributeMaxDynamicSharedMemorySize, SMEM_TOTAL);
        attr_done = true;
    }

    prep1_kernel<<<KK, 256>>>(M);
    int nb = (N + MROWS - 1) / MROWS;
    main_mma_kernel<<<nb, 256, SMEM_TOTAL>>>(X, pi, (float*)d_out, N, nb);
}